// round 5
// baseline (speedup 1.0000x reference)
#include <cuda_runtime.h>
#include <math.h>

#define NTOK 8192
#define CDIM 1024
#define HDIM 4096
#define NEXP 8
#define NSLOT (2*NTOK)
#define STAGES 3
#define BM 256
#define BN 128
#define BK 32
#define STAGE_F 12288   // floats per stage: A 256x32 (8192) + B 128x32 (4096)
#define SMEM_DYN (STAGES * STAGE_F * 4)   // 147456 bytes

// ---------------- device scratch (static, allocation-free) ----------------
__device__ int   g_counts[NEXP];
__device__ int   g_offsets[NEXP];
__device__ int   g_tokens[NEXP * NTOK];
__device__ float g_gate[NEXP * NTOK];
__device__ float g_h[(size_t)NSLOT * HDIM];            // tf32-rounded activations
__device__ float g_w1t[(size_t)NEXP * HDIM * CDIM];    // tf32-rounded weights
__device__ float g_w2t[(size_t)NEXP * CDIM * HDIM];
__device__ float g_xt[(size_t)NTOK * CDIM];            // tf32-rounded x

// ---------------- helpers ----------------
__device__ __forceinline__ float new_gelu(float v) {
    const float c = 0.7978845608028654f;
    float u = c * (v + 0.044715f * v * v * v);
    return 0.5f * v * (1.0f + tanhf(u));
}
__device__ __forceinline__ unsigned f2tf(float f) {
    unsigned u;
    asm("cvt.rna.tf32.f32 %0, %1;" : "=r"(u) : "f"(f));
    return u;
}
__device__ __forceinline__ void mma_tf32(float* c, const unsigned* a, const unsigned* b) {
    asm volatile(
        "mma.sync.aligned.m16n8k8.row.col.f32.tf32.tf32.f32 "
        "{%0,%1,%2,%3}, {%4,%5,%6,%7}, {%8,%9}, {%0,%1,%2,%3};"
        : "+f"(c[0]), "+f"(c[1]), "+f"(c[2]), "+f"(c[3])
        : "r"(a[0]), "r"(a[1]), "r"(a[2]), "r"(a[3]), "r"(b[0]), "r"(b[1]));
}
__device__ __forceinline__ void cp16(float* dst_smem, const float* src, int src_size) {
    unsigned sa = (unsigned)__cvta_generic_to_shared(dst_smem);
    asm volatile("cp.async.cg.shared.global [%0], [%1], 16, %2;"
                 :: "r"(sa), "l"(src), "r"(src_size));
}
__device__ __forceinline__ void cp_commit() {
    asm volatile("cp.async.commit_group;" ::: "memory");
}
template <int N>
__device__ __forceinline__ void cp_wait() {
    asm volatile("cp.async.wait_group %0;" :: "n"(N) : "memory");
}

// ---------------- kernel 0: reset counters ----------------
__global__ void init_kernel() {
    if (threadIdx.x < NEXP) g_counts[threadIdx.x] = 0;
}

// ---------------- prep: tf32-round weights and x into scratch -------------
__global__ void prep_kernel(const float* __restrict__ w1,
                            const float* __restrict__ w2,
                            const float* __restrict__ x) {
    const size_t N1 = (size_t)NEXP * HDIM * CDIM / 4;
    const size_t N2 = N1 * 2;
    const size_t N3 = N2 + (size_t)NTOK * CDIM / 4;
    size_t i = (size_t)blockIdx.x * 256 + threadIdx.x;
    if (i >= N3) return;
    float4 v; float4* o;
    if (i < N1)      { v = ((const float4*)w1)[i];      o = (float4*)g_w1t + i; }
    else if (i < N2) { v = ((const float4*)w2)[i - N1]; o = (float4*)g_w2t + (i - N1); }
    else             { v = ((const float4*)x)[i - N2];  o = (float4*)g_xt + (i - N2); }
    v.x = __uint_as_float(f2tf(v.x));
    v.y = __uint_as_float(f2tf(v.y));
    v.z = __uint_as_float(f2tf(v.z));
    v.w = __uint_as_float(f2tf(v.w));
    *o = v;
}

// ---------------- router (one warp per token) ----------------
__global__ void router_kernel(const float* __restrict__ x,
                              const float* __restrict__ rw) {
    int warp = (blockIdx.x * blockDim.x + threadIdx.x) >> 5;
    int lane = threadIdx.x & 31;
    if (warp >= NTOK) return;
    const float* xr = x + (size_t)warp * CDIM;

    float acc[NEXP];
#pragma unroll
    for (int e = 0; e < NEXP; e++) acc[e] = 0.f;
    for (int c = lane; c < CDIM; c += 32) {
        float xv = xr[c];
#pragma unroll
        for (int e = 0; e < NEXP; e++)
            acc[e] = fmaf(xv, rw[e * CDIM + c], acc[e]);
    }
#pragma unroll
    for (int off = 16; off > 0; off >>= 1)
#pragma unroll
        for (int e = 0; e < NEXP; e++)
            acc[e] += __shfl_xor_sync(0xffffffffu, acc[e], off);

    if (lane == 0) {
        float mx = acc[0];
#pragma unroll
        for (int e = 1; e < NEXP; e++) mx = fmaxf(mx, acc[e]);
        float p[NEXP], s = 0.f;
#pragma unroll
        for (int e = 0; e < NEXP; e++) { p[e] = expf(acc[e] - mx); s += p[e]; }
        float inv = 1.f / s;
#pragma unroll
        for (int e = 0; e < NEXP; e++) p[e] *= inv;

        int i0 = 0;
#pragma unroll
        for (int e = 1; e < NEXP; e++) if (p[e] > p[i0]) i0 = e;
        int i1 = (i0 == 0) ? 1 : 0;
#pragma unroll
        for (int e = 0; e < NEXP; e++)
            if (e != i0 && p[e] > p[i1]) i1 = e;

        float denom = p[i0] + p[i1] + 1e-8f;
        int pos0 = atomicAdd(&g_counts[i0], 1);
        g_tokens[i0 * NTOK + pos0] = warp;
        g_gate[i0 * NTOK + pos0]   = p[i0] / denom;
        int pos1 = atomicAdd(&g_counts[i1], 1);
        g_tokens[i1 * NTOK + pos1] = warp;
        g_gate[i1 * NTOK + pos1]   = p[i1] / denom;
    }
}

// ---------------- exclusive prefix ----------------
__global__ void offsets_kernel() {
    if (threadIdx.x == 0) {
        int s = 0;
        for (int e = 0; e < NEXP; e++) { g_offsets[e] = s; s += g_counts[e]; }
    }
}

// =====================================================================
// TF32 mma.sync grouped GEMM: BM=256 BN=128 BK=32, 512 threads (16 warps),
// warp tile 64x32. 3-stage cp.async pipeline. Operands pre-rounded tf32.
// smem stage: A[256][32] swizzled + B[128][32] swizzled.
// =====================================================================

__device__ __forceinline__ void compute_stage(
    const unsigned* __restrict__ As, const unsigned* __restrict__ Bs,
    int wm, int wn, int g, int t, float acc[4][4][4])
{
#pragma unroll
    for (int kk4 = 0; kk4 < 8; kk4 += 2) {
        unsigned a[4][4], b[4][2];
        int base0 = ((kk4 ^ g) << 2) + t;
        int base1 = (((kk4 + 1) ^ g) << 2) + t;
#pragma unroll
        for (int mi = 0; mi < 4; mi++) {
            int r0 = wm + mi * 16 + g;
            a[mi][0] = As[r0 * 32 + base0];
            a[mi][1] = As[(r0 + 8) * 32 + base0];
            a[mi][2] = As[r0 * 32 + base1];
            a[mi][3] = As[(r0 + 8) * 32 + base1];
        }
#pragma unroll
        for (int ni = 0; ni < 4; ni++) {
            int c0 = wn + ni * 8 + g;              // c0 & 7 == g
            b[ni][0] = Bs[c0 * 32 + base0];
            b[ni][1] = Bs[c0 * 32 + base1];
        }
#pragma unroll
        for (int mi = 0; mi < 4; mi++)
#pragma unroll
            for (int ni = 0; ni < 4; ni++)
                mma_tf32(acc[mi][ni], a[mi], b[ni]);
    }
}

// A loads: 4 chunks/thread (rows tid>>3 + 64j), B: 2 chunks/thread.
// swizzled float offset: row*32 + ((c ^ (row&7))<<2), c = tid&7 (constant).
#define GEMM_PIPELINE(Kdim)                                                   \
    const int tid  = threadIdx.x;                                             \
    const int lane = tid & 31;                                                \
    const int wid  = tid >> 5;                                                \
    const int wm   = (wid & 3) * 64;                                          \
    const int wn   = (wid >> 2) * 32;                                         \
    const int g    = lane >> 2;                                               \
    const int t    = lane & 3;                                                \
    const int lc   = tid & 7;                                                 \
    const int lr   = tid >> 3;                                                \
    float acc[4][4][4];                                                       \
    _Pragma("unroll")                                                         \
    for (int mi = 0; mi < 4; mi++)                                            \
        _Pragma("unroll")                                                     \
        for (int ni = 0; ni < 4; ni++)                                        \
            _Pragma("unroll")                                                 \
            for (int r = 0; r < 4; r++) acc[mi][ni][r] = 0.f;                 \
    extern __shared__ float smem[];                                           \
    auto issue = [&](int stage, int kt) {                                     \
        float* As_s = smem + stage * STAGE_F;                                 \
        float* Bs_s = As_s + 8192;                                            \
        _Pragma("unroll")                                                     \
        for (int j = 0; j < 4; j++) {                                         \
            int row = lr + j * 64;                                            \
            int off = row * 32 + ((lc ^ (row & 7)) << 2);                     \
            const float* sa = aRow[j] ? aRow[j] + kt + lc * 4 : bRow[0];      \
            cp16(As_s + off, sa, aRow[j] ? 16 : 0);                           \
        }                                                                     \
        _Pragma("unroll")                                                     \
        for (int j = 0; j < 2; j++) {                                         \
            int row = lr + j * 64;                                            \
            int off = row * 32 + ((lc ^ (row & 7)) << 2);                     \
            cp16(Bs_s + off, bRow[j] + kt + lc * 4, 16);                      \
        }                                                                     \
    };                                                                        \
    const int KT = (Kdim) / BK;                                               \
    issue(0, 0); cp_commit();                                                 \
    issue(1, BK); cp_commit();                                                \
    int cs = 0, ns = 2;                                                       \
    for (int i = 0; i < KT; i++) {                                            \
        cp_wait<STAGES - 2>();                                                \
        __syncthreads();                                                      \
        int ktn = (i + STAGES - 1) * BK;                                      \
        if (ktn < (Kdim)) issue(ns, ktn);                                     \
        cp_commit();                                                          \
        compute_stage((const unsigned*)(smem + cs * STAGE_F),                 \
                      (const unsigned*)(smem + cs * STAGE_F + 8192),          \
                      wm, wn, g, t, acc);                                     \
        if (++cs == STAGES) cs = 0;                                           \
        if (++ns == STAGES) ns = 0;                                           \
    }

// ---------------- GEMM1: g_h = tf32(gelu(xt[tok] @ w1t^T + b1)) -----------
__global__ void __launch_bounds__(512, 1)
gemm1_kernel(const float* __restrict__ b1) {
    const int e   = blockIdx.z;
    const int cnt = g_counts[e];
    const int m0  = blockIdx.y * BM;
    if (m0 >= cnt) return;
    const int n0  = blockIdx.x * BN;
    const int off = g_offsets[e];
    const float* w1e = g_w1t + (size_t)e * HDIM * CDIM;

    const float* aRow[4];
    const float* bRow[2];
    {
        const int r = threadIdx.x >> 3;
#pragma unroll
        for (int j = 0; j < 4; j++) {
            int gm = m0 + r + j * 64;
            aRow[j] = (gm < cnt) ? (g_xt + (size_t)g_tokens[e * NTOK + gm] * CDIM)
                                 : (const float*)0;
        }
#pragma unroll
        for (int j = 0; j < 2; j++)
            bRow[j] = w1e + (size_t)(n0 + r + j * 64) * CDIM;
    }

    GEMM_PIPELINE(CDIM)

#pragma unroll
    for (int mi = 0; mi < 4; mi++) {
        int r0 = m0 + wm + mi * 16 + g;
#pragma unroll
        for (int ni = 0; ni < 4; ni++) {
            int col = n0 + wn + ni * 8 + t * 2;
            float bv0 = b1[e * HDIM + col];
            float bv1 = b1[e * HDIM + col + 1];
            if (r0 < cnt) {
                float* h = g_h + (size_t)(off + r0) * HDIM + col;
                h[0] = __uint_as_float(f2tf(new_gelu(acc[mi][ni][0] + bv0)));
                h[1] = __uint_as_float(f2tf(new_gelu(acc[mi][ni][1] + bv1)));
            }
            if (r0 + 8 < cnt) {
                float* h = g_h + (size_t)(off + r0 + 8) * HDIM + col;
                h[0] = __uint_as_float(f2tf(new_gelu(acc[mi][ni][2] + bv0)));
                h[1] = __uint_as_float(f2tf(new_gelu(acc[mi][ni][3] + bv1)));
            }
        }
    }
}

// ---------------- GEMM2: out += gate * (h @ w2t^T + b2) -------------------
__global__ void __launch_bounds__(512, 1)
gemm2_kernel(const float* __restrict__ b2, float* __restrict__ out) {
    const int e   = blockIdx.z;
    const int cnt = g_counts[e];
    const int m0  = blockIdx.y * BM;
    if (m0 >= cnt) return;
    const int n0  = blockIdx.x * BN;
    const int off = g_offsets[e];
    const float* w2e = g_w2t + (size_t)e * CDIM * HDIM;

    const float* aRow[4];
    const float* bRow[2];
    {
        const int r = threadIdx.x >> 3;
#pragma unroll
        for (int j = 0; j < 4; j++) {
            int gm = m0 + r + j * 64;
            aRow[j] = (gm < cnt) ? (g_h + (size_t)(off + gm) * HDIM) : (const float*)0;
        }
#pragma unroll
        for (int j = 0; j < 2; j++)
            bRow[j] = w2e + (size_t)(n0 + r + j * 64) * HDIM;
    }

    GEMM_PIPELINE(HDIM)

#pragma unroll
    for (int mi = 0; mi < 4; mi++) {
        int r0 = m0 + wm + mi * 16 + g;
#pragma unroll
        for (int half = 0; half < 2; half++) {
            int gm = r0 + half * 8;
            if (gm >= cnt) continue;
            int token  = g_tokens[e * NTOK + gm];
            float gate = g_gate[e * NTOK + gm];
            float* orow = out + (size_t)token * CDIM;
#pragma unroll
            for (int ni = 0; ni < 4; ni++) {
                int col = n0 + wn + ni * 8 + t * 2;
                float v0 = acc[mi][ni][half * 2 + 0] + b2[e * CDIM + col];
                float v1 = acc[mi][ni][half * 2 + 1] + b2[e * CDIM + col + 1];
                atomicAdd(&orow[col], gate * v0);
                atomicAdd(&orow[col + 1], gate * v1);
            }
        }
    }
}

// ---------------- launch ----------------
extern "C" void kernel_launch(void* const* d_in, const int* in_sizes, int n_in,
                              void* d_out, int out_size) {
    const float* x  = (const float*)d_in[0];
    const float* rw = (const float*)d_in[1];
    const float* w1 = (const float*)d_in[2];
    const float* b1 = (const float*)d_in[3];
    const float* w2 = (const float*)d_in[4];
    const float* b2 = (const float*)d_in[5];
    float* out = (float*)d_out;

    cudaFuncSetAttribute(gemm1_kernel, cudaFuncAttributeMaxDynamicSharedMemorySize, SMEM_DYN);
    cudaFuncSetAttribute(gemm2_kernel, cudaFuncAttributeMaxDynamicSharedMemorySize, SMEM_DYN);

    cudaMemsetAsync(out, 0, (size_t)out_size * sizeof(float), 0);
    init_kernel<<<1, 32>>>();

    const size_t nprep = ((size_t)NEXP * HDIM * CDIM * 2 + (size_t)NTOK * CDIM) / 4;
    prep_kernel<<<(unsigned)((nprep + 255) / 256), 256>>>(w1, w2, x);

    router_kernel<<<(NTOK * 32 + 255) / 256, 256>>>(x, rw);
    offsets_kernel<<<1, 32>>>();

    dim3 g1(HDIM / BN, NTOK / BM, NEXP);
    gemm1_kernel<<<g1, 512, SMEM_DYN>>>(b1);

    dim3 g2(CDIM / BN, NTOK / BM, NEXP);
    gemm2_kernel<<<g2, 512, SMEM_DYN>>>(b2, out);
}

// round 6
// speedup vs baseline: 2.0402x; 2.0402x over previous
#include <cuda_runtime.h>
#include <cuda_fp16.h>
#include <math.h>

#define NTOK 8192
#define CDIM 1024
#define HDIM 4096
#define NEXP 8
#define NSLOT (2*NTOK)
#define STAGES 3
#define BM 128
#define BN 128
#define BK 64
// stage: A 128x64 fp16 (16KB) + B 128x64 fp16 (16KB) = 32KB
#define STAGE_U32 8192                     // uint32 units per stage
#define SMEM_DYN (STAGES * STAGE_U32 * 4)  // 98304 bytes

// ---------------- device scratch (static, allocation-free) ----------------
__device__ int    g_counts[NEXP];
__device__ int    g_offsets[NEXP];
__device__ int    g_tokens[NEXP * NTOK];
__device__ float  g_gate[NEXP * NTOK];
__device__ __half g_h[(size_t)NSLOT * HDIM];           // fp16 activations
__device__ __half g_w1h[(size_t)NEXP * HDIM * CDIM];   // fp16 weights
__device__ __half g_w2h[(size_t)NEXP * CDIM * HDIM];
__device__ __half g_xh[(size_t)NTOK * CDIM];           // fp16 x

// ---------------- helpers ----------------
__device__ __forceinline__ float new_gelu(float v) {
    const float c = 0.7978845608028654f;
    float u = c * (v + 0.044715f * v * v * v);
    return 0.5f * v * (1.0f + tanhf(u));
}
__device__ __forceinline__ void mma_f16(float* c, const unsigned* a, const unsigned* b) {
    asm volatile(
        "mma.sync.aligned.m16n8k16.row.col.f32.f16.f16.f32 "
        "{%0,%1,%2,%3}, {%4,%5,%6,%7}, {%8,%9}, {%0,%1,%2,%3};"
        : "+f"(c[0]), "+f"(c[1]), "+f"(c[2]), "+f"(c[3])
        : "r"(a[0]), "r"(a[1]), "r"(a[2]), "r"(a[3]), "r"(b[0]), "r"(b[1]));
}
__device__ __forceinline__ void cp16(void* dst_smem, const void* src, int src_size) {
    unsigned sa = (unsigned)__cvta_generic_to_shared(dst_smem);
    asm volatile("cp.async.cg.shared.global [%0], [%1], 16, %2;"
                 :: "r"(sa), "l"(src), "r"(src_size));
}
__device__ __forceinline__ void cp_commit() {
    asm volatile("cp.async.commit_group;" ::: "memory");
}
template <int N>
__device__ __forceinline__ void cp_wait() {
    asm volatile("cp.async.wait_group %0;" :: "n"(N) : "memory");
}
// swizzled uint32 index within a [128][32]-u32 tile (row = 64 fp16 = 128B)
__device__ __forceinline__ int swzi(int row, int c4, int t) {
    return row * 32 + (((c4) ^ (row & 7)) << 2) + t;
}

// ---------------- kernel 0: reset counters ----------------
__global__ void init_kernel() {
    if (threadIdx.x < NEXP) g_counts[threadIdx.x] = 0;
}

// ---------------- prep: fp16-convert weights and x ----------------
__global__ void prep_kernel(const float* __restrict__ w1,
                            const float* __restrict__ w2,
                            const float* __restrict__ x) {
    const size_t N1 = (size_t)NEXP * HDIM * CDIM / 4;
    const size_t N2 = N1 * 2;
    const size_t N3 = N2 + (size_t)NTOK * CDIM / 4;
    size_t i = (size_t)blockIdx.x * 256 + threadIdx.x;
    if (i >= N3) return;
    float4 v; __half2* o;
    if (i < N1)      { v = ((const float4*)w1)[i];      o = (__half2*)g_w1h + i * 2; }
    else if (i < N2) { v = ((const float4*)w2)[i - N1]; o = (__half2*)g_w2h + (i - N1) * 2; }
    else             { v = ((const float4*)x)[i - N2];  o = (__half2*)g_xh  + (i - N2) * 2; }
    o[0] = __floats2half2_rn(v.x, v.y);
    o[1] = __floats2half2_rn(v.z, v.w);
}

// ---------------- router (one warp per token) ----------------
__global__ void router_kernel(const float* __restrict__ x,
                              const float* __restrict__ rw) {
    int warp = (blockIdx.x * blockDim.x + threadIdx.x) >> 5;
    int lane = threadIdx.x & 31;
    if (warp >= NTOK) return;
    const float* xr = x + (size_t)warp * CDIM;

    float acc[NEXP];
#pragma unroll
    for (int e = 0; e < NEXP; e++) acc[e] = 0.f;
    for (int c = lane; c < CDIM; c += 32) {
        float xv = xr[c];
#pragma unroll
        for (int e = 0; e < NEXP; e++)
            acc[e] = fmaf(xv, rw[e * CDIM + c], acc[e]);
    }
#pragma unroll
    for (int off = 16; off > 0; off >>= 1)
#pragma unroll
        for (int e = 0; e < NEXP; e++)
            acc[e] += __shfl_xor_sync(0xffffffffu, acc[e], off);

    if (lane == 0) {
        float mx = acc[0];
#pragma unroll
        for (int e = 1; e < NEXP; e++) mx = fmaxf(mx, acc[e]);
        float p[NEXP], s = 0.f;
#pragma unroll
        for (int e = 0; e < NEXP; e++) { p[e] = expf(acc[e] - mx); s += p[e]; }
        float inv = 1.f / s;
#pragma unroll
        for (int e = 0; e < NEXP; e++) p[e] *= inv;

        int i0 = 0;
#pragma unroll
        for (int e = 1; e < NEXP; e++) if (p[e] > p[i0]) i0 = e;
        int i1 = (i0 == 0) ? 1 : 0;
#pragma unroll
        for (int e = 0; e < NEXP; e++)
            if (e != i0 && p[e] > p[i1]) i1 = e;

        float denom = p[i0] + p[i1] + 1e-8f;
        int pos0 = atomicAdd(&g_counts[i0], 1);
        g_tokens[i0 * NTOK + pos0] = warp;
        g_gate[i0 * NTOK + pos0]   = p[i0] / denom;
        int pos1 = atomicAdd(&g_counts[i1], 1);
        g_tokens[i1 * NTOK + pos1] = warp;
        g_gate[i1 * NTOK + pos1]   = p[i1] / denom;
    }
}

// ---------------- exclusive prefix ----------------
__global__ void offsets_kernel() {
    if (threadIdx.x == 0) {
        int s = 0;
        for (int e = 0; e < NEXP; e++) { g_offsets[e] = s; s += g_counts[e]; }
    }
}

// =====================================================================
// FP16 mma.sync grouped GEMM: BM=128 BN=128 BK=64, 256 threads (8 warps),
// warp tile 64x32, m16n8k16, fp32 accum. 3-stage cp.async pipeline.
// =====================================================================

__device__ __forceinline__ void compute_stage(
    const unsigned* __restrict__ As, const unsigned* __restrict__ Bs,
    int wm, int wn, int g, int t, float acc[4][4][4])
{
#pragma unroll
    for (int kk = 0; kk < 4; kk++) {          // 4 x k16
        unsigned a[4][4], b[4][2];
        const int c4lo = kk * 2, c4hi = kk * 2 + 1;
#pragma unroll
        for (int mi = 0; mi < 4; mi++) {
            int r0 = wm + mi * 16 + g;
            a[mi][0] = As[swzi(r0,     c4lo, t)];
            a[mi][1] = As[swzi(r0 + 8, c4lo, t)];
            a[mi][2] = As[swzi(r0,     c4hi, t)];
            a[mi][3] = As[swzi(r0 + 8, c4hi, t)];
        }
#pragma unroll
        for (int ni = 0; ni < 4; ni++) {
            int c0 = wn + ni * 8 + g;
            b[ni][0] = Bs[swzi(c0, c4lo, t)];
            b[ni][1] = Bs[swzi(c0, c4hi, t)];
        }
#pragma unroll
        for (int mi = 0; mi < 4; mi++)
#pragma unroll
            for (int ni = 0; ni < 4; ni++)
                mma_f16(acc[mi][ni], a[mi], b[ni]);
    }
}

// Loaders: row stride 64 fp16 = 8 x 16B chunks; thread -> (lr = tid>>3, lc = tid&7)
// 4 A chunks (rows lr+32j) + 4 B chunks.
#define GEMM_PIPELINE(Kdim)                                                   \
    const int tid  = threadIdx.x;                                             \
    const int lane = tid & 31;                                                \
    const int wid  = tid >> 5;                                                \
    const int wm   = (wid & 1) * 64;                                          \
    const int wn   = (wid >> 1) * 32;                                         \
    const int g    = lane >> 2;                                               \
    const int t    = lane & 3;                                                \
    const int lc   = tid & 7;                                                 \
    const int lr   = tid >> 3;                                                \
    float acc[4][4][4];                                                       \
    _Pragma("unroll")                                                         \
    for (int mi = 0; mi < 4; mi++)                                            \
        _Pragma("unroll")                                                     \
        for (int ni = 0; ni < 4; ni++)                                        \
            _Pragma("unroll")                                                 \
            for (int r = 0; r < 4; r++) acc[mi][ni][r] = 0.f;                 \
    extern __shared__ unsigned smem[];                                        \
    auto issue = [&](int stage, int kt) {                                     \
        unsigned* As_s = smem + stage * STAGE_U32;                            \
        unsigned* Bs_s = As_s + 4096;                                         \
        _Pragma("unroll")                                                     \
        for (int j = 0; j < 4; j++) {                                         \
            int row = lr + j * 32;                                            \
            int off = row * 32 + ((lc ^ (row & 7)) << 2);                     \
            const __half* sa = aRow[j] ? aRow[j] + kt + lc * 8                \
                                       : (const __half*)bRow[0];              \
            cp16(As_s + off, sa, aRow[j] ? 16 : 0);                           \
            cp16(Bs_s + off, bRow[j] + kt + lc * 8, 16);                      \
        }                                                                     \
    };                                                                        \
    const int KT = (Kdim) / BK;                                               \
    issue(0, 0); cp_commit();                                                 \
    issue(1, BK); cp_commit();                                                \
    int cs = 0, ns = 2;                                                       \
    for (int i = 0; i < KT; i++) {                                            \
        cp_wait<STAGES - 2>();                                                \
        __syncthreads();                                                      \
        int ktn = (i + STAGES - 1) * BK;                                      \
        if (ktn < (Kdim)) issue(ns, ktn);                                     \
        cp_commit();                                                          \
        compute_stage(smem + cs * STAGE_U32, smem + cs * STAGE_U32 + 4096,    \
                      wm, wn, g, t, acc);                                     \
        if (++cs == STAGES) cs = 0;                                           \
        if (++ns == STAGES) ns = 0;                                           \
    }

// ---------------- GEMM1: g_h = fp16(gelu(xh[tok] @ w1h^T + b1)) -----------
__global__ void __launch_bounds__(256, 2)
gemm1_kernel(const float* __restrict__ b1) {
    const int e   = blockIdx.z;
    const int cnt = g_counts[e];
    const int m0  = blockIdx.y * BM;
    if (m0 >= cnt) return;
    const int n0  = blockIdx.x * BN;
    const int off = g_offsets[e];
    const __half* w1e = g_w1h + (size_t)e * HDIM * CDIM;

    const __half* aRow[4];
    const __half* bRow[4];
    {
        const int r = threadIdx.x >> 3;
#pragma unroll
        for (int j = 0; j < 4; j++) {
            int gm = m0 + r + j * 32;
            aRow[j] = (gm < cnt) ? (g_xh + (size_t)g_tokens[e * NTOK + gm] * CDIM)
                                 : (const __half*)0;
            bRow[j] = w1e + (size_t)(n0 + r + j * 32) * CDIM;
        }
    }

    GEMM_PIPELINE(CDIM)

#pragma unroll
    for (int mi = 0; mi < 4; mi++) {
        int r0 = m0 + wm + mi * 16 + g;
#pragma unroll
        for (int ni = 0; ni < 4; ni++) {
            int col = n0 + wn + ni * 8 + t * 2;
            float bv0 = b1[e * HDIM + col];
            float bv1 = b1[e * HDIM + col + 1];
            if (r0 < cnt) {
                __half2* h = (__half2*)(g_h + (size_t)(off + r0) * HDIM + col);
                *h = __floats2half2_rn(new_gelu(acc[mi][ni][0] + bv0),
                                       new_gelu(acc[mi][ni][1] + bv1));
            }
            if (r0 + 8 < cnt) {
                __half2* h = (__half2*)(g_h + (size_t)(off + r0 + 8) * HDIM + col);
                *h = __floats2half2_rn(new_gelu(acc[mi][ni][2] + bv0),
                                       new_gelu(acc[mi][ni][3] + bv1));
            }
        }
    }
}

// ---------------- GEMM2: out += gate * (h @ w2h^T + b2) -------------------
__global__ void __launch_bounds__(256, 2)
gemm2_kernel(const float* __restrict__ b2, float* __restrict__ out) {
    const int e   = blockIdx.z;
    const int cnt = g_counts[e];
    const int m0  = blockIdx.y * BM;
    if (m0 >= cnt) return;
    const int n0  = blockIdx.x * BN;
    const int off = g_offsets[e];
    const __half* w2e = g_w2h + (size_t)e * CDIM * HDIM;

    const __half* aRow[4];
    const __half* bRow[4];
    {
        const int r = threadIdx.x >> 3;
#pragma unroll
        for (int j = 0; j < 4; j++) {
            int gm = m0 + r + j * 32;
            aRow[j] = (gm < cnt) ? (g_h + (size_t)(off + gm) * HDIM) : (const __half*)0;
            bRow[j] = w2e + (size_t)(n0 + r + j * 32) * HDIM;
        }
    }

    GEMM_PIPELINE(HDIM)

#pragma unroll
    for (int mi = 0; mi < 4; mi++) {
        int r0 = m0 + wm + mi * 16 + g;
#pragma unroll
        for (int half = 0; half < 2; half++) {
            int gm = r0 + half * 8;
            if (gm >= cnt) continue;
            int token  = g_tokens[e * NTOK + gm];
            float gate = g_gate[e * NTOK + gm];
            float* orow = out + (size_t)token * CDIM;
#pragma unroll
            for (int ni = 0; ni < 4; ni++) {
                int col = n0 + wn + ni * 8 + t * 2;
                float v0 = acc[mi][ni][half * 2 + 0] + b2[e * CDIM + col];
                float v1 = acc[mi][ni][half * 2 + 1] + b2[e * CDIM + col + 1];
                atomicAdd(&orow[col], gate * v0);
                atomicAdd(&orow[col + 1], gate * v1);
            }
        }
    }
}

// ---------------- launch ----------------
extern "C" void kernel_launch(void* const* d_in, const int* in_sizes, int n_in,
                              void* d_out, int out_size) {
    const float* x  = (const float*)d_in[0];
    const float* rw = (const float*)d_in[1];
    const float* w1 = (const float*)d_in[2];
    const float* b1 = (const float*)d_in[3];
    const float* w2 = (const float*)d_in[4];
    const float* b2 = (const float*)d_in[5];
    float* out = (float*)d_out;

    cudaFuncSetAttribute(gemm1_kernel, cudaFuncAttributeMaxDynamicSharedMemorySize, SMEM_DYN);
    cudaFuncSetAttribute(gemm2_kernel, cudaFuncAttributeMaxDynamicSharedMemorySize, SMEM_DYN);

    cudaMemsetAsync(out, 0, (size_t)out_size * sizeof(float), 0);
    init_kernel<<<1, 32>>>();

    const size_t nprep = ((size_t)NEXP * HDIM * CDIM * 2 + (size_t)NTOK * CDIM) / 4;
    prep_kernel<<<(unsigned)((nprep + 255) / 256), 256>>>(w1, w2, x);

    router_kernel<<<(NTOK * 32 + 255) / 256, 256>>>(x, rw);
    offsets_kernel<<<1, 32>>>();

    dim3 g1(HDIM / BN, NTOK / BM, NEXP);
    gemm1_kernel<<<g1, 256, SMEM_DYN>>>(b1);

    dim3 g2(CDIM / BN, NTOK / BM, NEXP);
    gemm2_kernel<<<g2, 256, SMEM_DYN>>>(b2, out);
}

// round 7
// speedup vs baseline: 2.1859x; 1.0714x over previous
#include <cuda_runtime.h>
#include <cuda_fp16.h>
#include <math.h>

#define NTOK 8192
#define CDIM 1024
#define HDIM 4096
#define NEXP 8
#define NSLOT (2*NTOK)
#define STAGES 3
#define BM 128
#define BN 128
#define BK 64
#define STAGE_U32 8192                     // uint32 per stage (A 16KB + B 16KB)
#define STAGE_BYTES (STAGE_U32 * 4)
#define SMEM_DYN (STAGES * STAGE_BYTES)    // 98304 bytes

// ---------------- device scratch (static, allocation-free) ----------------
__device__ int    g_counts[NEXP];
__device__ int    g_tokens[NEXP * NTOK];
__device__ float  g_gate[NEXP * NTOK];
__device__ __half g_h[(size_t)NSLOT * HDIM];
__device__ __half g_w1h[(size_t)NEXP * HDIM * CDIM];
__device__ __half g_w2h[(size_t)NEXP * CDIM * HDIM];
__device__ __half g_xh[(size_t)NTOK * CDIM];

// ---------------- helpers ----------------
__device__ __forceinline__ float new_gelu(float v) {
    const float c = 0.7978845608028654f;
    float u = c * (v + 0.044715f * v * v * v);
    return 0.5f * v * (1.0f + tanhf(u));
}
__device__ __forceinline__ void mma_f16(float* c, const unsigned* a, const unsigned* b) {
    asm volatile(
        "mma.sync.aligned.m16n8k16.row.col.f32.f16.f16.f32 "
        "{%0,%1,%2,%3}, {%4,%5,%6,%7}, {%8,%9}, {%0,%1,%2,%3};"
        : "+f"(c[0]), "+f"(c[1]), "+f"(c[2]), "+f"(c[3])
        : "r"(a[0]), "r"(a[1]), "r"(a[2]), "r"(a[3]), "r"(b[0]), "r"(b[1]));
}
__device__ __forceinline__ void ldm_x4(unsigned* r, unsigned addr) {
    asm volatile("ldmatrix.sync.aligned.m8n8.x4.shared.b16 {%0,%1,%2,%3}, [%4];"
                 : "=r"(r[0]), "=r"(r[1]), "=r"(r[2]), "=r"(r[3]) : "r"(addr));
}
__device__ __forceinline__ void cp16(unsigned dst, const void* src, int src_size) {
    asm volatile("cp.async.cg.shared.global [%0], [%1], 16, %2;"
                 :: "r"(dst), "l"(src), "r"(src_size));
}
__device__ __forceinline__ void cp_commit() {
    asm volatile("cp.async.commit_group;" ::: "memory");
}
template <int N>
__device__ __forceinline__ void cp_wait() {
    asm volatile("cp.async.wait_group %0;" :: "n"(N) : "memory");
}

// ---------------- kernel 0: reset counters ----------------
__global__ void init_kernel() {
    if (threadIdx.x < NEXP) g_counts[threadIdx.x] = 0;
}

// ---------------- prep: fp16-convert weights and x ----------------
__global__ void prep_kernel(const float* __restrict__ w1,
                            const float* __restrict__ w2,
                            const float* __restrict__ x) {
    const size_t N1 = (size_t)NEXP * HDIM * CDIM / 4;
    const size_t N2 = N1 * 2;
    const size_t N3 = N2 + (size_t)NTOK * CDIM / 4;
    size_t i = (size_t)blockIdx.x * 256 + threadIdx.x;
    if (i >= N3) return;
    float4 v; __half2* o;
    if (i < N1)      { v = ((const float4*)w1)[i];      o = (__half2*)g_w1h + i * 2; }
    else if (i < N2) { v = ((const float4*)w2)[i - N1]; o = (__half2*)g_w2h + (i - N1) * 2; }
    else             { v = ((const float4*)x)[i - N2];  o = (__half2*)g_xh  + (i - N2) * 2; }
    o[0] = __floats2half2_rn(v.x, v.y);
    o[1] = __floats2half2_rn(v.z, v.w);
}

// ---------------- router (one warp per token) ----------------
__global__ void router_kernel(const float* __restrict__ x,
                              const float* __restrict__ rw) {
    int warp = (blockIdx.x * blockDim.x + threadIdx.x) >> 5;
    int lane = threadIdx.x & 31;
    if (warp >= NTOK) return;
    const float* xr = x + (size_t)warp * CDIM;

    float acc[NEXP];
#pragma unroll
    for (int e = 0; e < NEXP; e++) acc[e] = 0.f;
    for (int c = lane; c < CDIM; c += 32) {
        float xv = xr[c];
#pragma unroll
        for (int e = 0; e < NEXP; e++)
            acc[e] = fmaf(xv, rw[e * CDIM + c], acc[e]);
    }
#pragma unroll
    for (int off = 16; off > 0; off >>= 1)
#pragma unroll
        for (int e = 0; e < NEXP; e++)
            acc[e] += __shfl_xor_sync(0xffffffffu, acc[e], off);

    if (lane == 0) {
        float mx = acc[0];
#pragma unroll
        for (int e = 1; e < NEXP; e++) mx = fmaxf(mx, acc[e]);
        float p[NEXP], s = 0.f;
#pragma unroll
        for (int e = 0; e < NEXP; e++) { p[e] = expf(acc[e] - mx); s += p[e]; }
        float inv = 1.f / s;
#pragma unroll
        for (int e = 0; e < NEXP; e++) p[e] *= inv;

        int i0 = 0;
#pragma unroll
        for (int e = 1; e < NEXP; e++) if (p[e] > p[i0]) i0 = e;
        int i1 = (i0 == 0) ? 1 : 0;
#pragma unroll
        for (int e = 0; e < NEXP; e++)
            if (e != i0 && p[e] > p[i1]) i1 = e;

        float denom = p[i0] + p[i1] + 1e-8f;
        int pos0 = atomicAdd(&g_counts[i0], 1);
        g_tokens[i0 * NTOK + pos0] = warp;
        g_gate[i0 * NTOK + pos0]   = p[i0] / denom;
        int pos1 = atomicAdd(&g_counts[i1], 1);
        g_tokens[i1 * NTOK + pos1] = warp;
        g_gate[i1 * NTOK + pos1]   = p[i1] / denom;
    }
}

// =====================================================================
// FP16 mma.sync grouped GEMM: BM=128 BN=128 BK=64, 256 threads (8 warps),
// warp tile 64x32, m16n8k16, fp32 accum, ldmatrix fragment loads.
// smem stage: A[128 rows][64 halves] swizzled (16B chunk c XOR row&7) + B same.
// =====================================================================

struct LdmCtx {
    unsigned aOff[4], bOff[2];   // byte offsets of this lane's ldmatrix row
    unsigned aSw[4], bSw[2];     // row & 7 (swizzle key)
    unsigned qh, ql;             // lane quadrant bits
};

__device__ __forceinline__ void ldm_setup(LdmCtx& c, int lane, int wm, int wn) {
    int rr = lane & 7, q = lane >> 3;
    c.qh = q >> 1; c.ql = q & 1;
#pragma unroll
    for (int mi = 0; mi < 4; mi++) {
        int row = wm + mi * 16 + c.ql * 8 + rr;     // A: ql picks row-half
        c.aOff[mi] = row * 128;
        c.aSw[mi]  = row & 7;
    }
#pragma unroll
    for (int p = 0; p < 2; p++) {
        int row = wn + (2 * p + c.qh) * 8 + rr;     // B: qh picks n-group
        c.bOff[p] = row * 128;
        c.bSw[p]  = row & 7;
    }
}

__device__ __forceinline__ void compute_stage(unsigned As, unsigned Bs,
                                              const LdmCtx& c, float acc[4][4][4]) {
#pragma unroll
    for (int kk = 0; kk < 4; kk++) {
        unsigned a[4][4], b[2][4];
        const unsigned ca = kk * 2 + c.qh;          // A chunk: qh picks k-half
        const unsigned cb = kk * 2 + c.ql;          // B chunk: ql picks k-half
#pragma unroll
        for (int mi = 0; mi < 4; mi++)
            ldm_x4(a[mi], As + c.aOff[mi] + (((ca ^ c.aSw[mi])) << 4));
#pragma unroll
        for (int p = 0; p < 2; p++)
            ldm_x4(b[p], Bs + c.bOff[p] + (((cb ^ c.bSw[p])) << 4));
#pragma unroll
        for (int mi = 0; mi < 4; mi++) {
            mma_f16(acc[mi][0], a[mi], &b[0][0]);
            mma_f16(acc[mi][1], a[mi], &b[0][2]);
            mma_f16(acc[mi][2], a[mi], &b[1][0]);
            mma_f16(acc[mi][3], a[mi], &b[1][2]);
        }
    }
}

#define GEMM_PIPELINE(Kdim)                                                   \
    const int tid  = threadIdx.x;                                             \
    const int lane = tid & 31;                                                \
    const int wid  = tid >> 5;                                                \
    const int wm   = (wid & 1) * 64;                                          \
    const int wn   = (wid >> 1) * 32;                                         \
    const int g    = lane >> 2;                                               \
    const int t    = lane & 3;                                                \
    const int lc   = tid & 7;                                                 \
    const int lr   = tid >> 3;                                                \
    float acc[4][4][4];                                                       \
    _Pragma("unroll")                                                         \
    for (int mi = 0; mi < 4; mi++)                                            \
        _Pragma("unroll")                                                     \
        for (int ni = 0; ni < 4; ni++)                                        \
            _Pragma("unroll")                                                 \
            for (int r = 0; r < 4; r++) acc[mi][ni][r] = 0.f;                 \
    extern __shared__ unsigned smem[];                                        \
    const unsigned sbase = (unsigned)__cvta_generic_to_shared(smem);          \
    LdmCtx lctx; ldm_setup(lctx, lane, wm, wn);                               \
    const unsigned ldOff = lr * 128 + ((lc ^ (lr & 7)) << 4);                 \
    auto issue = [&](int stage, int kt) {                                     \
        unsigned As_s = sbase + stage * STAGE_BYTES;                          \
        unsigned Bs_s = As_s + 16384;                                         \
        _Pragma("unroll")                                                     \
        for (int j = 0; j < 4; j++) {                                         \
            unsigned off = ldOff + j * 32 * 128;                              \
            const __half* sa = aRow[j] ? aRow[j] + kt + lc * 8                \
                                       : (const __half*)bRow[0];              \
            cp16(As_s + off, sa, aRow[j] ? 16 : 0);                           \
            cp16(Bs_s + off, bRow[j] + kt + lc * 8, 16);                      \
        }                                                                     \
    };                                                                        \
    const int KT = (Kdim) / BK;                                               \
    issue(0, 0); cp_commit();                                                 \
    issue(1, BK); cp_commit();                                                \
    int cs = 0, ns = 2;                                                       \
    for (int i = 0; i < KT; i++) {                                            \
        cp_wait<STAGES - 2>();                                                \
        __syncthreads();                                                      \
        int ktn = (i + STAGES - 1) * BK;                                      \
        if (ktn < (Kdim)) issue(ns, ktn);                                     \
        cp_commit();                                                          \
        compute_stage(sbase + cs * STAGE_BYTES,                               \
                      sbase + cs * STAGE_BYTES + 16384, lctx, acc);           \
        if (++cs == STAGES) cs = 0;                                           \
        if (++ns == STAGES) ns = 0;                                           \
    }

__device__ __forceinline__ int expert_offset(int e) {
    int off = 0;
#pragma unroll
    for (int k = 0; k < NEXP; k++) if (k < e) off += g_counts[k];
    return off;
}

// ---------------- GEMM1: g_h = fp16(gelu(xh[tok] @ w1h^T + b1)) -----------
__global__ void __launch_bounds__(256, 2)
gemm1_kernel(const float* __restrict__ b1) {
    const int e   = blockIdx.z;
    const int cnt = g_counts[e];
    const int m0  = blockIdx.y * BM;
    if (m0 >= cnt) return;
    const int n0  = blockIdx.x * BN;
    const int off = expert_offset(e);
    const __half* w1e = g_w1h + (size_t)e * HDIM * CDIM;

    const __half* aRow[4];
    const __half* bRow[4];
    {
        const int r = threadIdx.x >> 3;
#pragma unroll
        for (int j = 0; j < 4; j++) {
            int gm = m0 + r + j * 32;
            aRow[j] = (gm < cnt) ? (g_xh + (size_t)g_tokens[e * NTOK + gm] * CDIM)
                                 : (const __half*)0;
            bRow[j] = w1e + (size_t)(n0 + r + j * 32) * CDIM;
        }
    }

    GEMM_PIPELINE(CDIM)

#pragma unroll
    for (int mi = 0; mi < 4; mi++) {
        int r0 = m0 + wm + mi * 16 + g;
#pragma unroll
        for (int ni = 0; ni < 4; ni++) {
            int col = n0 + wn + ni * 8 + t * 2;
            float bv0 = b1[e * HDIM + col];
            float bv1 = b1[e * HDIM + col + 1];
            if (r0 < cnt) {
                __half2* h = (__half2*)(g_h + (size_t)(off + r0) * HDIM + col);
                *h = __floats2half2_rn(new_gelu(acc[mi][ni][0] + bv0),
                                       new_gelu(acc[mi][ni][1] + bv1));
            }
            if (r0 + 8 < cnt) {
                __half2* h = (__half2*)(g_h + (size_t)(off + r0 + 8) * HDIM + col);
                *h = __floats2half2_rn(new_gelu(acc[mi][ni][2] + bv0),
                                       new_gelu(acc[mi][ni][3] + bv1));
            }
        }
    }
}

// ---------------- GEMM2: out += gate * (h @ w2h^T + b2) -------------------
__global__ void __launch_bounds__(256, 2)
gemm2_kernel(const float* __restrict__ b2, float* __restrict__ out) {
    const int e   = blockIdx.z;
    const int cnt = g_counts[e];
    const int m0  = blockIdx.y * BM;
    if (m0 >= cnt) return;
    const int n0  = blockIdx.x * BN;
    const int off = expert_offset(e);
    const __half* w2e = g_w2h + (size_t)e * CDIM * HDIM;

    const __half* aRow[4];
    const __half* bRow[4];
    {
        const int r = threadIdx.x >> 3;
#pragma unroll
        for (int j = 0; j < 4; j++) {
            int gm = m0 + r + j * 32;
            aRow[j] = (gm < cnt) ? (g_h + (size_t)(off + gm) * HDIM) : (const __half*)0;
            bRow[j] = w2e + (size_t)(n0 + r + j * 32) * HDIM;
        }
    }

    GEMM_PIPELINE(HDIM)

#pragma unroll
    for (int mi = 0; mi < 4; mi++) {
        int r0 = m0 + wm + mi * 16 + g;
#pragma unroll
        for (int half = 0; half < 2; half++) {
            int gm = r0 + half * 8;
            if (gm >= cnt) continue;
            int token  = g_tokens[e * NTOK + gm];
            float gate = g_gate[e * NTOK + gm];
            float* orow = out + (size_t)token * CDIM;
#pragma unroll
            for (int ni = 0; ni < 4; ni++) {
                int col = n0 + wn + ni * 8 + t * 2;
                float v0 = acc[mi][ni][half * 2 + 0] + b2[e * CDIM + col];
                float v1 = acc[mi][ni][half * 2 + 1] + b2[e * CDIM + col + 1];
                atomicAdd(&orow[col], gate * v0);
                atomicAdd(&orow[col + 1], gate * v1);
            }
        }
    }
}

// ---------------- launch ----------------
extern "C" void kernel_launch(void* const* d_in, const int* in_sizes, int n_in,
                              void* d_out, int out_size) {
    const float* x  = (const float*)d_in[0];
    const float* rw = (const float*)d_in[1];
    const float* w1 = (const float*)d_in[2];
    const float* b1 = (const float*)d_in[3];
    const float* w2 = (const float*)d_in[4];
    const float* b2 = (const float*)d_in[5];
    float* out = (float*)d_out;

    cudaFuncSetAttribute(gemm1_kernel, cudaFuncAttributeMaxDynamicSharedMemorySize, SMEM_DYN);
    cudaFuncSetAttribute(gemm2_kernel, cudaFuncAttributeMaxDynamicSharedMemorySize, SMEM_DYN);

    cudaMemsetAsync(out, 0, (size_t)out_size * sizeof(float), 0);
    init_kernel<<<1, 32>>>();

    const size_t nprep = ((size_t)NEXP * HDIM * CDIM * 2 + (size_t)NTOK * CDIM) / 4;
    prep_kernel<<<(unsigned)((nprep + 255) / 256), 256>>>(w1, w2, x);

    router_kernel<<<(NTOK * 32 + 255) / 256, 256>>>(x, rw);

    dim3 g1(HDIM / BN, NTOK / BM, NEXP);
    gemm1_kernel<<<g1, 256, SMEM_DYN>>>(b1);

    dim3 g2(CDIM / BN, NTOK / BM, NEXP);
    gemm2_kernel<<<g2, 256, SMEM_DYN>>>(b2, out);
}